// round 16
// baseline (speedup 1.0000x reference)
#include <cuda_runtime.h>
#include <cuda_fp16.h>
#include <cstdint>

#define D       512
#define NCLS    9
#define EPSF    1e-5f
#define E_PAD   150016   // 150000 padded to multiple of 128
#define CHUNKS  8        // K=512 in chunks of 64
#define STAGES  3
#define STG_B   32768u   // A 16KB + W 16KB per stage
#define CPAD    136      // padded smem row stride (halves) for C staging
#define BN_TBL  2048u    // smem bytes for BN half2 table (256 x uint2)

// ---------------- scratch (bss; no runtime allocation) ---------------------
__device__ __align__(128) __half g_a[(size_t)E_PAD * D];   // GEMM1 in / GEMM2 out
__device__ __align__(128) __half g_hh[(size_t)E_PAD * D];  // GEMM1 out / GEMM2 in
__device__ __align__(128) __half g_w1h[512 * 512];         // W1 fp16
__device__ __align__(128) __half g_w2h[512 * 512];         // W2 fp16
__device__ float g_sum[D];
__device__ float g_sumsq[D];
__device__ float g_sc[D];
__device__ float g_sh[D];
__device__ uint2 g_bn[D / 2];   // packed {half2 sc, half2 sh} per 2 columns

// ======================= PTX helpers (sm_100-safe) ==========================
__device__ __forceinline__ uint32_t smem_to_u32(const void* p) {
    uint32_t a;
    asm("{ .reg .u64 t; cvta.to.shared.u64 t, %1; cvt.u32.u64 %0, t; }" : "=r"(a) : "l"(p));
    return a;
}
#define CP_ASYNC16(dst, src) \
    asm volatile("cp.async.cg.shared.global [%0], [%1], 16;" :: "r"(dst), "l"(src) : "memory")
#define CP_COMMIT() asm volatile("cp.async.commit_group;" ::: "memory")
#define LDM_X4(r, addr) \
    asm volatile("ldmatrix.sync.aligned.m8n8.x4.shared.b16 {%0,%1,%2,%3}, [%4];" \
        : "=r"((r)[0]), "=r"((r)[1]), "=r"((r)[2]), "=r"((r)[3]) : "r"(addr))
#define MMA_FP16(d, a, b0, b1) \
    asm volatile("mma.sync.aligned.m16n8k16.row.col.f32.f16.f16.f32 " \
        "{%0,%1,%2,%3}, {%4,%5,%6,%7}, {%8,%9}, {%0,%1,%2,%3};" \
        : "+f"((d)[0]), "+f"((d)[1]), "+f"((d)[2]), "+f"((d)[3]) \
        : "r"((a)[0]), "r"((a)[1]), "r"((a)[2]), "r"((a)[3]), "r"(b0), "r"(b1))

// ---------------- 1) gather + add + LayerNorm -> fp16 (warp per edge) ------
// Tail blocks (>= gblocks) convert both weight matrices fp32->fp16.
// Block 0 also zeroes the BN1 stats accumulators.
__global__ void gather_ln(const float* __restrict__ x,
                          const int* __restrict__ src,
                          const int* __restrict__ dst,
                          const float* __restrict__ lnw,
                          __half* __restrict__ A, int E, int gblocks,
                          const float* __restrict__ W1,
                          const float* __restrict__ W2,
                          __half* __restrict__ Wh1,
                          __half* __restrict__ Wh2)
{
    if (blockIdx.x >= gblocks) {
        // weight conversion: 1024 tail blocks x 256 threads = 262144 elems
        const int idx = (blockIdx.x - gblocks) * 256 + threadIdx.x;
        Wh1[idx] = __float2half(W1[idx]);
        Wh2[idx] = __float2half(W2[idx]);
        return;
    }
    if (blockIdx.x == 0) {
        for (int c = threadIdx.x; c < D; c += blockDim.x) {
            g_sum[c] = 0.0f;
            g_sumsq[c] = 0.0f;
        }
    }
    const int e = (blockIdx.x * blockDim.x + threadIdx.x) >> 5;
    if (e >= E) return;
    const int lane = threadIdx.x & 31;

    const float* xs = x + (size_t)src[e] * D;
    const float* xd = x + (size_t)dst[e] * D;

    float4 v[4];
    float s = 0.0f;
    #pragma unroll
    for (int q = 0; q < 4; q++) {
        const int c = q * 128 + lane * 4;
        float4 a = *(const float4*)(xs + c);
        float4 b = *(const float4*)(xd + c);
        v[q] = make_float4(a.x + b.x, a.y + b.y, a.z + b.z, a.w + b.w);
        s += v[q].x + v[q].y + v[q].z + v[q].w;
    }
    #pragma unroll
    for (int o = 16; o; o >>= 1) s += __shfl_xor_sync(0xffffffffu, s, o);
    const float mu = s * (1.0f / D);

    float ss = 0.0f;
    #pragma unroll
    for (int q = 0; q < 4; q++) {
        v[q].x -= mu; v[q].y -= mu; v[q].z -= mu; v[q].w -= mu;
        ss += v[q].x * v[q].x + v[q].y * v[q].y + v[q].z * v[q].z + v[q].w * v[q].w;
    }
    #pragma unroll
    for (int o = 16; o; o >>= 1) ss += __shfl_xor_sync(0xffffffffu, ss, o);
    const float rs = rsqrtf(ss * (1.0f / D) + EPSF);

    __half* arow = A + (size_t)e * D;
    #pragma unroll
    for (int q = 0; q < 4; q++) {
        const int c = q * 128 + lane * 4;
        float4 w = *(const float4*)(lnw + c);
        union { __half h[4]; uint2 u; } pk;
        pk.h[0] = __float2half(v[q].x * rs * w.x);
        pk.h[1] = __float2half(v[q].y * rs * w.y);
        pk.h[2] = __float2half(v[q].z * rs * w.z);
        pk.h[3] = __float2half(v[q].w * rs * w.w);
        *(uint2*)(arow + c) = pk.u;
    }
}

// ---------------- fp16 mma.sync GEMM (+opt fused BN+ReLU on A) -------------
// C[M,512] (fp16, smem-staged coalesced stores) = act(A)[M,512] @ W^T;
// act = identity (BNAPP=0) or per-column relu(a*sc+sh) in fp16 (BNAPP=1).
// Also accumulates per-column fp32 sum / sumsq of C (rows < E) into
// g_sum / g_sumsq. CTA tile 128x128, 8 warps (4Mx2N of 32x64 warp tiles),
// 8 chunks of K=64 (ROLLED loop — full unroll regressed: I$), 3-stage
// cp.async, 2 CTAs/SM.
#define GEMM_SMEM (BN_TBL + STAGES * 32768)

template <bool BNAPP>
__global__ void __launch_bounds__(256, 2)
bgemm(const __half* __restrict__ A, const __half* __restrict__ W,
      __half* __restrict__ C, int E)
{
    extern __shared__ __align__(128) char smem[];
    const int tid = threadIdx.x;
    const int lane = tid & 31, wid = tid >> 5;
    const int m0 = blockIdx.y * 128;
    const int n0 = blockIdx.x * 128;
    const uint32_t sbase = smem_to_u32(smem) + BN_TBL;   // stage region

    // BN table -> smem (2KB); visible after first mainloop barrier
    if (BNAPP && tid < 256) *((uint2*)smem + tid) = g_bn[tid];

    // ---- cp.async mapping: thread -> (row = tid/2, 4 groups of 16B) ----
    const int lrow = tid >> 1;
    const int lg0  = (tid & 1) * 4;
    const __half* Abase = A + (size_t)(m0 + lrow) * D + lg0 * 8;
    const __half* Wbase = W + (size_t)(n0 + lrow) * D + lg0 * 8;
    uint32_t dsw[4];
    #pragma unroll
    for (int q = 0; q < 4; q++)
        dsw[q] = (uint32_t)(lrow * 128 + ((lg0 + q) ^ (lrow & 7)) * 16);

    // ---- ldmatrix fragment addresses (warp 32x64) ----
    const int wm = (wid & 3) * 32;        // warp M offset
    const int wn = (wid >> 2) * 64;       // warp N offset
    const int ar = wm + (lane & 15);                       // + mf*16
    const int agsel = lane >> 4;
    const int br = wn + (lane & 7) + ((lane >> 4) << 3);   // + np*16
    const int bgsel = (lane >> 3) & 1;

    float acc[2][8][4];
    #pragma unroll
    for (int i = 0; i < 2; i++)
        #pragma unroll
        for (int j = 0; j < 8; j++)
            #pragma unroll
            for (int q = 0; q < 4; q++) acc[i][j][q] = 0.0f;

    // issue chunk i (K offset i*64) into stage st
    auto issue = [&](int i, int st) {
        const char* aps = (const char*)(Abase + i * 64);
        const char* wps = (const char*)(Wbase + i * 64);
        const uint32_t da = sbase + st * STG_B;
        const uint32_t dw = da + 16384u;
        #pragma unroll
        for (int q = 0; q < 4; q++) {
            CP_ASYNC16(da + dsw[q], aps + q * 16);
            CP_ASYNC16(dw + dsw[q], wps + q * 16);
        }
        CP_COMMIT();
    };

    const uint2* bntbl = (const uint2*)smem;
    auto compute = [&](int st, int ci) {
        const uint32_t sA = sbase + st * STG_B;
        const uint32_t sW = sA + 16384u;
        #pragma unroll
        for (int kk = 0; kk < 4; kk++) {
            const int kg2 = kk * 2;
            uint32_t a[2][4];
            #pragma unroll
            for (int mf = 0; mf < 2; mf++) {
                const int r = ar + mf * 16;
                const int g = kg2 + agsel;
                LDM_X4(a[mf], sA + r * 128 + ((g ^ (r & 7)) * 16));
            }
            if (BNAPP) {
                const int bidx = ci * 32 + kk * 8 + (lane & 3);
                uint2 lo = bntbl[bidx];
                uint2 hi = bntbl[bidx + 4];
                const __half2 sc_lo = *(const __half2*)&lo.x;
                const __half2 sh_lo = *(const __half2*)&lo.y;
                const __half2 sc_hi = *(const __half2*)&hi.x;
                const __half2 sh_hi = *(const __half2*)&hi.y;
                #pragma unroll
                for (int mf = 0; mf < 2; mf++) {
                    __half2 v;
                    v = __hfma2_relu(*(__half2*)&a[mf][0], sc_lo, sh_lo);
                    a[mf][0] = *(uint32_t*)&v;
                    v = __hfma2_relu(*(__half2*)&a[mf][1], sc_lo, sh_lo);
                    a[mf][1] = *(uint32_t*)&v;
                    v = __hfma2_relu(*(__half2*)&a[mf][2], sc_hi, sh_hi);
                    a[mf][2] = *(uint32_t*)&v;
                    v = __hfma2_relu(*(__half2*)&a[mf][3], sc_hi, sh_hi);
                    a[mf][3] = *(uint32_t*)&v;
                }
            }
            #pragma unroll
            for (int np = 0; np < 4; np++) {
                const int r = br + np * 16;
                const int g = kg2 + bgsel;
                uint32_t b[4];
                LDM_X4(b, sW + r * 128 + ((g ^ (r & 7)) * 16));
                #pragma unroll
                for (int mf = 0; mf < 2; mf++) {
                    MMA_FP16(acc[mf][np * 2],     a[mf], b[0], b[1]);
                    MMA_FP16(acc[mf][np * 2 + 1], a[mf], b[2], b[3]);
                }
            }
        }
    };

    // ---- 3-stage mainloop (ROLLED): wait -> sync -> issue(i+2) -> compute -
    issue(0, 0);
    issue(1, 1);
    #pragma unroll 1
    for (int i = 0; i < CHUNKS; i++) {
        if (i < CHUNKS - 1)
            asm volatile("cp.async.wait_group 1;" ::: "memory");
        else
            asm volatile("cp.async.wait_group 0;" ::: "memory");
        __syncthreads();
        if (i + 2 < CHUNKS) issue(i + 2, (i + 2) % STAGES);
        compute(i % STAGES, i);
    }

    // ---- epilogue: fragments -> smem (fp16) -> coalesced global stores ----
    float*  ssum = (float*)(smem + BN_TBL);          // 128 floats
    float*  ssq  = (float*)(smem + BN_TBL) + 128;    // 128 floats
    __half* Csm  = (__half*)(smem + BN_TBL + 1024);  // 128 x CPAD halves

    __syncthreads();                                 // mainloop smem reads done
    if (tid < 128) { ssum[tid] = 0.0f; ssq[tid] = 0.0f; }

    const int cq = (lane & 3) * 2;
    const int rq = lane >> 2;
    #pragma unroll
    for (int mf = 0; mf < 2; mf++) {
        const int row = wm + mf * 16 + rq;
        #pragma unroll
        for (int nf = 0; nf < 8; nf++) {
            const int col = wn + nf * 8 + cq;
            *(__half2*)(Csm + row * CPAD + col) =
                __floats2half2_rn(acc[mf][nf][0], acc[mf][nf][1]);
            *(__half2*)(Csm + (row + 8) * CPAD + col) =
                __floats2half2_rn(acc[mf][nf][2], acc[mf][nf][3]);
        }
    }
    __syncthreads();                                 // Csm + ssum zero visible

    // coalesced stores: thread -> (row = tid/2, 64-halves half-row)
    {
        const int srow = tid >> 1;
        const int scol = (tid & 1) * 64;
        const __half* srcp = Csm + srow * CPAD + scol;
        __half* dstp = C + (size_t)(m0 + srow) * D + n0 + scol;  // E_PAD rows
        #pragma unroll
        for (int j = 0; j < 8; j++)
            *(uint4*)(dstp + j * 8) = *(const uint4*)(srcp + j * 8);
    }

    // fused BN column stats (fp32, from registers; rows >= E masked out)
    float msk[2][2];
    #pragma unroll
    for (int mf = 0; mf < 2; mf++) {
        msk[mf][0] = (m0 + wm + mf * 16 + rq     < E) ? 1.0f : 0.0f;
        msk[mf][1] = (m0 + wm + mf * 16 + rq + 8 < E) ? 1.0f : 0.0f;
    }
    #pragma unroll
    for (int nf = 0; nf < 8; nf++) {
        #pragma unroll
        for (int p = 0; p < 2; p++) {
            float s = 0.0f, q = 0.0f;
            #pragma unroll
            for (int mf = 0; mf < 2; mf++) {
                float v0 = acc[mf][nf][p]     * msk[mf][0];
                float v1 = acc[mf][nf][p + 2] * msk[mf][1];
                s += v0 + v1;
                q += v0 * v0 + v1 * v1;
            }
            #pragma unroll
            for (int mk = 4; mk <= 16; mk <<= 1) {
                s += __shfl_xor_sync(0xffffffffu, s, mk);
                q += __shfl_xor_sync(0xffffffffu, q, mk);
            }
            if (lane < 4) {
                const int cl = wn + nf * 8 + (lane & 3) * 2 + p;
                atomicAdd(&ssum[cl], s);
                atomicAdd(&ssq[cl], q);
            }
        }
    }
    __syncthreads();
    if (tid < 128) {
        atomicAdd(&g_sum[n0 + tid], ssum[tid]);
        atomicAdd(&g_sumsq[n0 + tid], ssq[tid]);
    }
}

// ---------------- stats finalize + BN table pack + stats reset -------------
__global__ void finalize_stats(const float* __restrict__ g,
                               const float* __restrict__ b, float invE)
{
    __shared__ float s_sc[D], s_sh[D];
    const int c = threadIdx.x;
    const float mean = g_sum[c] * invE;
    const float var  = g_sumsq[c] * invE - mean * mean;
    const float istd = rsqrtf(var + EPSF);
    const float scv  = istd * g[c];
    const float shv  = fmaf(-mean, scv, b[c]);
    g_sc[c] = scv;
    g_sh[c] = shv;
    s_sc[c] = scv;
    s_sh[c] = shv;
    g_sum[c] = 0.0f;        // reset for next BN accumulation
    g_sumsq[c] = 0.0f;
    __syncthreads();
    if (c < D / 2) {
        __half2 sc2 = __floats2half2_rn(s_sc[2 * c], s_sc[2 * c + 1]);
        __half2 sh2 = __floats2half2_rn(s_sh[2 * c], s_sh[2 * c + 1]);
        g_bn[c] = make_uint2(*(uint32_t*)&sc2, *(uint32_t*)&sh2);
    }
}

// ---------------- head: out[E,9] = relu(BN(H)) @ Wout^T (fp16 H) -----------
__global__ void head(const __half* __restrict__ H,
                     const float* __restrict__ Wout,
                     float* __restrict__ out, int E)
{
    __shared__ float Ws[NCLS * D];
    for (int i = threadIdx.x; i < NCLS * D; i += blockDim.x) Ws[i] = Wout[i];
    __syncthreads();

    const int warp = threadIdx.x >> 5, lane = threadIdx.x & 31;
    const int row = blockIdx.x * 8 + warp;
    if (row >= E) return;

    const __half* hp = H + (size_t)row * D;
    float acc[NCLS];
    #pragma unroll
    for (int j = 0; j < NCLS; j++) acc[j] = 0.0f;

    #pragma unroll
    for (int i = 0; i < D / 256; i++) {          // 2 iters: uint4 = 8 halves
        const int k = (lane + i * 32) * 8;
        union { __half2 h2[4]; uint4 u; } hv;
        hv.u = *(const uint4*)(hp + k);
        #pragma unroll
        for (int m = 0; m < 4; m++) {
            float2 vf = __half22float2(hv.h2[m]);
            const int kk = k + m * 2;
            const float v0 = fmaxf(fmaf(vf.x, g_sc[kk],     g_sh[kk]),     0.0f);
            const float v1 = fmaxf(fmaf(vf.y, g_sc[kk + 1], g_sh[kk + 1]), 0.0f);
            #pragma unroll
            for (int j = 0; j < NCLS; j++)
                acc[j] = fmaf(v1, Ws[j * D + kk + 1], fmaf(v0, Ws[j * D + kk], acc[j]));
        }
    }
    #pragma unroll
    for (int j = 0; j < NCLS; j++)
        #pragma unroll
        for (int o = 16; o; o >>= 1)
            acc[j] += __shfl_down_sync(0xffffffffu, acc[j], o);

    if (lane == 0) {
        #pragma unroll
        for (int j = 0; j < NCLS; j++) out[(size_t)row * NCLS + j] = acc[j];
    }
}

// ---------------- launch ---------------------------------------------------
extern "C" void kernel_launch(void* const* d_in, const int* in_sizes, int n_in,
                              void* d_out, int out_size)
{
    const float* x    = (const float*)d_in[0];
    const int*   src  = (const int*)d_in[1];
    const int*   dst  = (const int*)d_in[2];
    const float* lnw  = (const float*)d_in[3];
    const float* W1   = (const float*)d_in[4];
    const float* g1   = (const float*)d_in[5];
    const float* b1   = (const float*)d_in[6];
    const float* W2   = (const float*)d_in[7];
    const float* g2   = (const float*)d_in[8];
    const float* b2   = (const float*)d_in[9];
    const float* Wout = (const float*)d_in[10];
    float* out = (float*)d_out;

    const int E = in_sizes[1];
    const float invE = 1.0f / (float)E;
    const int mtiles = (E + 127) / 128;
    const int gblocks = (E + 7) / 8;

    void *pa, *phh, *pw1, *pw2;
    cudaGetSymbolAddress(&pa, g_a);
    cudaGetSymbolAddress(&phh, g_hh);
    cudaGetSymbolAddress(&pw1, g_w1h);
    cudaGetSymbolAddress(&pw2, g_w2h);

    cudaFuncSetAttribute(bgemm<false>, cudaFuncAttributeMaxDynamicSharedMemorySize, GEMM_SMEM);
    cudaFuncSetAttribute(bgemm<true>,  cudaFuncAttributeMaxDynamicSharedMemorySize, GEMM_SMEM);

    __half* A  = (__half*)pa;    // GEMM1 input, GEMM2 output
    __half* h1 = (__half*)phh;   // GEMM1 output, GEMM2 input

    // 1) gather + LN -> A (fp16), zeroes BN1 stats; tail blocks convert W1/W2
    gather_ln<<<gblocks + 1024, 256>>>(x, src, dst, lnw, A, E, gblocks,
                                       W1, W2, (__half*)pw1, (__half*)pw2);

    // 2) GEMM1 (+ fused BN1 stats): h1 = A @ W1^T
    bgemm<false><<<dim3(4, mtiles), 256, GEMM_SMEM>>>(A, (__half*)pw1, h1, E);
    finalize_stats<<<1, D>>>(g1, b1, invE);   // sc1/sh1 + BN table + reset

    // 3) GEMM2 with fused BN1+ReLU on A-load (+ fused BN2 stats): A = BN(h1) @ W2^T
    bgemm<true><<<dim3(4, mtiles), 256, GEMM_SMEM>>>(h1, (__half*)pw2, A, E);
    finalize_stats<<<1, D>>>(g2, b2, invE);   // sc2/sh2

    // 4) head reads h2 (=A) with BN2+ReLU
    head<<<(E + 7) / 8, 256>>>(A, Wout, out, E);
}

// round 17
// speedup vs baseline: 1.1721x; 1.1721x over previous
#include <cuda_runtime.h>
#include <cuda_fp16.h>
#include <cstdint>

#define D       512
#define NCLS    9
#define EPSF    1e-5f
#define E_PAD   150016   // 150000 padded to multiple of 128
#define CHUNKS  8        // K=512 in chunks of 64
#define STAGES  3
#define STG_B   32768u   // A 16KB + W 16KB per stage
#define CPAD    136      // padded smem row stride (halves) for C staging
#define BN_TBL  2048u    // smem bytes for BN half2 table (256 x uint2)

// ---------------- scratch (bss; no runtime allocation) ---------------------
__device__ __align__(128) __half g_a[(size_t)E_PAD * D];   // GEMM1 in / GEMM2 out
__device__ __align__(128) __half g_hh[(size_t)E_PAD * D];  // GEMM1 out / GEMM2 in
__device__ __align__(128) __half g_w1h[512 * 512];         // W1 fp16
__device__ __align__(128) __half g_w2h[512 * 512];         // W2 fp16
__device__ float g_sum[D];
__device__ float g_sumsq[D];
__device__ float g_sc[D];
__device__ float g_sh[D];
__device__ uint2 g_bn[D / 2];   // packed {half2 sc, half2 sh} per 2 columns

// ======================= PTX helpers (sm_100-safe) ==========================
__device__ __forceinline__ uint32_t smem_to_u32(const void* p) {
    uint32_t a;
    asm("{ .reg .u64 t; cvta.to.shared.u64 t, %1; cvt.u32.u64 %0, t; }" : "=r"(a) : "l"(p));
    return a;
}
#define CP_ASYNC16(dst, src) \
    asm volatile("cp.async.cg.shared.global [%0], [%1], 16;" :: "r"(dst), "l"(src) : "memory")
#define CP_COMMIT() asm volatile("cp.async.commit_group;" ::: "memory")
#define LDM_X4(r, addr) \
    asm volatile("ldmatrix.sync.aligned.m8n8.x4.shared.b16 {%0,%1,%2,%3}, [%4];" \
        : "=r"((r)[0]), "=r"((r)[1]), "=r"((r)[2]), "=r"((r)[3]) : "r"(addr))
#define MMA_FP16(d, a, b0, b1) \
    asm volatile("mma.sync.aligned.m16n8k16.row.col.f32.f16.f16.f32 " \
        "{%0,%1,%2,%3}, {%4,%5,%6,%7}, {%8,%9}, {%0,%1,%2,%3};" \
        : "+f"((d)[0]), "+f"((d)[1]), "+f"((d)[2]), "+f"((d)[3]) \
        : "r"((a)[0]), "r"((a)[1]), "r"((a)[2]), "r"((a)[3]), "r"(b0), "r"(b1))

// ---------------- 1) gather + add + LayerNorm -> fp16 (warp per edge) ------
// Block 0 also zeroes the BN1 stats accumulators (completes before bgemm1).
__global__ void gather_ln(const float* __restrict__ x,
                          const int* __restrict__ src,
                          const int* __restrict__ dst,
                          const float* __restrict__ lnw,
                          __half* __restrict__ A, int E)
{
    if (blockIdx.x == 0) {
        for (int c = threadIdx.x; c < D; c += blockDim.x) {
            g_sum[c] = 0.0f;
            g_sumsq[c] = 0.0f;
        }
    }
    const int e = (blockIdx.x * blockDim.x + threadIdx.x) >> 5;
    if (e >= E) return;
    const int lane = threadIdx.x & 31;

    const float* xs = x + (size_t)src[e] * D;
    const float* xd = x + (size_t)dst[e] * D;

    float4 v[4];
    float s = 0.0f;
    #pragma unroll
    for (int q = 0; q < 4; q++) {
        const int c = q * 128 + lane * 4;
        float4 a = *(const float4*)(xs + c);
        float4 b = *(const float4*)(xd + c);
        v[q] = make_float4(a.x + b.x, a.y + b.y, a.z + b.z, a.w + b.w);
        s += v[q].x + v[q].y + v[q].z + v[q].w;
    }
    #pragma unroll
    for (int o = 16; o; o >>= 1) s += __shfl_xor_sync(0xffffffffu, s, o);
    const float mu = s * (1.0f / D);

    float ss = 0.0f;
    #pragma unroll
    for (int q = 0; q < 4; q++) {
        v[q].x -= mu; v[q].y -= mu; v[q].z -= mu; v[q].w -= mu;
        ss += v[q].x * v[q].x + v[q].y * v[q].y + v[q].z * v[q].z + v[q].w * v[q].w;
    }
    #pragma unroll
    for (int o = 16; o; o >>= 1) ss += __shfl_xor_sync(0xffffffffu, ss, o);
    const float rs = rsqrtf(ss * (1.0f / D) + EPSF);

    __half* arow = A + (size_t)e * D;
    #pragma unroll
    for (int q = 0; q < 4; q++) {
        const int c = q * 128 + lane * 4;
        float4 w = *(const float4*)(lnw + c);
        union { __half h[4]; uint2 u; } pk;
        pk.h[0] = __float2half(v[q].x * rs * w.x);
        pk.h[1] = __float2half(v[q].y * rs * w.y);
        pk.h[2] = __float2half(v[q].z * rs * w.z);
        pk.h[3] = __float2half(v[q].w * rs * w.w);
        *(uint2*)(arow + c) = pk.u;
    }
}

// ---------------- weight convert: both W fp32 -> fp16 ----------------------
__global__ void wconv2(const float* __restrict__ W1, const float* __restrict__ W2,
                       __half* __restrict__ Wh1, __half* __restrict__ Wh2)
{
    const int idx = blockIdx.x * blockDim.x + threadIdx.x;   // 512*512 threads
    Wh1[idx] = __float2half(W1[idx]);
    Wh2[idx] = __float2half(W2[idx]);
}

// ---------------- fp16 mma.sync GEMM (+opt fused BN+ReLU on A) -------------
// C[M,512] (fp16, smem-staged coalesced stores) = act(A)[M,512] @ W^T;
// act = identity (BNAPP=0) or per-column relu(a*sc+sh) in fp16 (BNAPP=1).
// Also accumulates per-column fp32 sum / sumsq of C (rows < E) into
// g_sum / g_sumsq. CTA tile 128x128, 8 warps (4Mx2N of 32x64 warp tiles),
// 8 chunks of K=64, 3-stage cp.async pipeline, 2 CTAs/SM.
#define GEMM_SMEM (BN_TBL + STAGES * 32768)

template <bool BNAPP>
__global__ void __launch_bounds__(256, 2)
bgemm(const __half* __restrict__ A, const __half* __restrict__ W,
      __half* __restrict__ C, int E)
{
    extern __shared__ __align__(128) char smem[];
    const int tid = threadIdx.x;
    const int lane = tid & 31, wid = tid >> 5;
    const int m0 = blockIdx.y * 128;
    const int n0 = blockIdx.x * 128;
    const uint32_t sbase = smem_to_u32(smem) + BN_TBL;   // stage region

    // BN table -> smem (2KB); visible after first mainloop barrier
    if (BNAPP && tid < 256) *((uint2*)smem + tid) = g_bn[tid];

    // ---- cp.async mapping: thread -> (row = tid/2, 4 groups of 16B) ----
    const int lrow = tid >> 1;
    const int lg0  = (tid & 1) * 4;
    const __half* Abase = A + (size_t)(m0 + lrow) * D + lg0 * 8;
    const __half* Wbase = W + (size_t)(n0 + lrow) * D + lg0 * 8;
    uint32_t dsw[4];
    #pragma unroll
    for (int q = 0; q < 4; q++)
        dsw[q] = (uint32_t)(lrow * 128 + ((lg0 + q) ^ (lrow & 7)) * 16);

    // ---- ldmatrix fragment addresses (warp 32x64) ----
    const int wm = (wid & 3) * 32;        // warp M offset
    const int wn = (wid >> 2) * 64;       // warp N offset
    const int ar = wm + (lane & 15);                       // + mf*16
    const int agsel = lane >> 4;
    const int br = wn + (lane & 7) + ((lane >> 4) << 3);   // + np*16
    const int bgsel = (lane >> 3) & 1;

    float acc[2][8][4];
    #pragma unroll
    for (int i = 0; i < 2; i++)
        #pragma unroll
        for (int j = 0; j < 8; j++)
            #pragma unroll
            for (int q = 0; q < 4; q++) acc[i][j][q] = 0.0f;

    // issue chunk i (K offset i*64) into stage st
    auto issue = [&](int i, int st) {
        const char* aps = (const char*)(Abase + i * 64);
        const char* wps = (const char*)(Wbase + i * 64);
        const uint32_t da = sbase + st * STG_B;
        const uint32_t dw = da + 16384u;
        #pragma unroll
        for (int q = 0; q < 4; q++) {
            CP_ASYNC16(da + dsw[q], aps + q * 16);
            CP_ASYNC16(dw + dsw[q], wps + q * 16);
        }
        CP_COMMIT();
    };

    const uint2* bntbl = (const uint2*)smem;
    auto compute = [&](int st, int ci) {
        const uint32_t sA = sbase + st * STG_B;
        const uint32_t sW = sA + 16384u;
        #pragma unroll
        for (int kk = 0; kk < 4; kk++) {
            const int kg2 = kk * 2;
            uint32_t a[2][4];
            #pragma unroll
            for (int mf = 0; mf < 2; mf++) {
                const int r = ar + mf * 16;
                const int g = kg2 + agsel;
                LDM_X4(a[mf], sA + r * 128 + ((g ^ (r & 7)) * 16));
            }
            if (BNAPP) {
                const int bidx = ci * 32 + kk * 8 + (lane & 3);
                uint2 lo = bntbl[bidx];
                uint2 hi = bntbl[bidx + 4];
                const __half2 sc_lo = *(const __half2*)&lo.x;
                const __half2 sh_lo = *(const __half2*)&lo.y;
                const __half2 sc_hi = *(const __half2*)&hi.x;
                const __half2 sh_hi = *(const __half2*)&hi.y;
                #pragma unroll
                for (int mf = 0; mf < 2; mf++) {
                    __half2 v;
                    v = __hfma2_relu(*(__half2*)&a[mf][0], sc_lo, sh_lo);
                    a[mf][0] = *(uint32_t*)&v;
                    v = __hfma2_relu(*(__half2*)&a[mf][1], sc_lo, sh_lo);
                    a[mf][1] = *(uint32_t*)&v;
                    v = __hfma2_relu(*(__half2*)&a[mf][2], sc_hi, sh_hi);
                    a[mf][2] = *(uint32_t*)&v;
                    v = __hfma2_relu(*(__half2*)&a[mf][3], sc_hi, sh_hi);
                    a[mf][3] = *(uint32_t*)&v;
                }
            }
            #pragma unroll
            for (int np = 0; np < 4; np++) {
                const int r = br + np * 16;
                const int g = kg2 + bgsel;
                uint32_t b[4];
                LDM_X4(b, sW + r * 128 + ((g ^ (r & 7)) * 16));
                #pragma unroll
                for (int mf = 0; mf < 2; mf++) {
                    MMA_FP16(acc[mf][np * 2],     a[mf], b[0], b[1]);
                    MMA_FP16(acc[mf][np * 2 + 1], a[mf], b[2], b[3]);
                }
            }
        }
    };

    // ---- 3-stage mainloop: wait -> barrier -> issue(i+2) -> compute(i) ----
    issue(0, 0);
    issue(1, 1);
    #pragma unroll 1
    for (int i = 0; i < CHUNKS; i++) {
        if (i < CHUNKS - 1)
            asm volatile("cp.async.wait_group 1;" ::: "memory");
        else
            asm volatile("cp.async.wait_group 0;" ::: "memory");
        __syncthreads();
        if (i + 2 < CHUNKS) issue(i + 2, (i + 2) % STAGES);
        compute(i % STAGES, i);
    }

    // ---- epilogue: fragments -> smem (fp16) -> coalesced global stores ----
    float*  ssum = (float*)(smem + BN_TBL);          // 128 floats
    float*  ssq  = (float*)(smem + BN_TBL) + 128;    // 128 floats
    __half* Csm  = (__half*)(smem + BN_TBL + 1024);  // 128 x CPAD halves

    __syncthreads();                                 // mainloop smem reads done
    if (tid < 128) { ssum[tid] = 0.0f; ssq[tid] = 0.0f; }

    const int cq = (lane & 3) * 2;
    const int rq = lane >> 2;
    #pragma unroll
    for (int mf = 0; mf < 2; mf++) {
        const int row = wm + mf * 16 + rq;
        #pragma unroll
        for (int nf = 0; nf < 8; nf++) {
            const int col = wn + nf * 8 + cq;
            *(__half2*)(Csm + row * CPAD + col) =
                __floats2half2_rn(acc[mf][nf][0], acc[mf][nf][1]);
            *(__half2*)(Csm + (row + 8) * CPAD + col) =
                __floats2half2_rn(acc[mf][nf][2], acc[mf][nf][3]);
        }
    }
    __syncthreads();                                 // Csm + ssum zero visible

    // coalesced stores: thread -> (row = tid/2, 64-halves half-row)
    {
        const int srow = tid >> 1;
        const int scol = (tid & 1) * 64;
        const __half* srcp = Csm + srow * CPAD + scol;
        __half* dstp = C + (size_t)(m0 + srow) * D + n0 + scol;  // E_PAD rows
        #pragma unroll
        for (int j = 0; j < 8; j++)
            *(uint4*)(dstp + j * 8) = *(const uint4*)(srcp + j * 8);
    }

    // fused BN column stats (fp32, from registers; rows >= E masked out)
    float msk[2][2];
    #pragma unroll
    for (int mf = 0; mf < 2; mf++) {
        msk[mf][0] = (m0 + wm + mf * 16 + rq     < E) ? 1.0f : 0.0f;
        msk[mf][1] = (m0 + wm + mf * 16 + rq + 8 < E) ? 1.0f : 0.0f;
    }
    #pragma unroll
    for (int nf = 0; nf < 8; nf++) {
        #pragma unroll
        for (int p = 0; p < 2; p++) {
            float s = 0.0f, q = 0.0f;
            #pragma unroll
            for (int mf = 0; mf < 2; mf++) {
                float v0 = acc[mf][nf][p]     * msk[mf][0];
                float v1 = acc[mf][nf][p + 2] * msk[mf][1];
                s += v0 + v1;
                q += v0 * v0 + v1 * v1;
            }
            #pragma unroll
            for (int mk = 4; mk <= 16; mk <<= 1) {
                s += __shfl_xor_sync(0xffffffffu, s, mk);
                q += __shfl_xor_sync(0xffffffffu, q, mk);
            }
            if (lane < 4) {
                const int cl = wn + nf * 8 + (lane & 3) * 2 + p;
                atomicAdd(&ssum[cl], s);
                atomicAdd(&ssq[cl], q);
            }
        }
    }
    __syncthreads();
    if (tid < 128) {
        atomicAdd(&g_sum[n0 + tid], ssum[tid]);
        atomicAdd(&g_sumsq[n0 + tid], ssq[tid]);
    }
}

// ---------------- stats finalize + BN table pack + stats reset -------------
__global__ void finalize_stats(const float* __restrict__ g,
                               const float* __restrict__ b, float invE)
{
    __shared__ float s_sc[D], s_sh[D];
    const int c = threadIdx.x;
    const float mean = g_sum[c] * invE;
    const float var  = g_sumsq[c] * invE - mean * mean;
    const float istd = rsqrtf(var + EPSF);
    const float scv  = istd * g[c];
    const float shv  = fmaf(-mean, scv, b[c]);
    g_sc[c] = scv;
    g_sh[c] = shv;
    s_sc[c] = scv;
    s_sh[c] = shv;
    g_sum[c] = 0.0f;        // reset for next BN accumulation
    g_sumsq[c] = 0.0f;
    __syncthreads();
    if (c < D / 2) {
        __half2 sc2 = __floats2half2_rn(s_sc[2 * c], s_sc[2 * c + 1]);
        __half2 sh2 = __floats2half2_rn(s_sh[2 * c], s_sh[2 * c + 1]);
        g_bn[c] = make_uint2(*(uint32_t*)&sc2, *(uint32_t*)&sh2);
    }
}

// ---------------- head: out[E,9] = relu(BN(H)) @ Wout^T (fp16 H) -----------
__global__ void head(const __half* __restrict__ H,
                     const float* __restrict__ Wout,
                     float* __restrict__ out, int E)
{
    __shared__ float Ws[NCLS * D];
    for (int i = threadIdx.x; i < NCLS * D; i += blockDim.x) Ws[i] = Wout[i];
    __syncthreads();

    const int warp = threadIdx.x >> 5, lane = threadIdx.x & 31;
    const int row = blockIdx.x * 8 + warp;
    if (row >= E) return;

    const __half* hp = H + (size_t)row * D;
    float acc[NCLS];
    #pragma unroll
    for (int j = 0; j < NCLS; j++) acc[j] = 0.0f;

    #pragma unroll
    for (int i = 0; i < D / 64; i++) {
        const int k = (lane + i * 32) * 2;
        __half2 hv = *(const __half2*)(hp + k);
        float2 vf = __half22float2(hv);
        const float v0 = fmaxf(fmaf(vf.x, g_sc[k],     g_sh[k]),     0.0f);
        const float v1 = fmaxf(fmaf(vf.y, g_sc[k + 1], g_sh[k + 1]), 0.0f);
        #pragma unroll
        for (int j = 0; j < NCLS; j++)
            acc[j] = fmaf(v1, Ws[j * D + k + 1], fmaf(v0, Ws[j * D + k], acc[j]));
    }
    #pragma unroll
    for (int j = 0; j < NCLS; j++)
        #pragma unroll
        for (int o = 16; o; o >>= 1)
            acc[j] += __shfl_down_sync(0xffffffffu, acc[j], o);

    if (lane == 0) {
        #pragma unroll
        for (int j = 0; j < NCLS; j++) out[(size_t)row * NCLS + j] = acc[j];
    }
}

// ---------------- launch ---------------------------------------------------
extern "C" void kernel_launch(void* const* d_in, const int* in_sizes, int n_in,
                              void* d_out, int out_size)
{
    const float* x    = (const float*)d_in[0];
    const int*   src  = (const int*)d_in[1];
    const int*   dst  = (const int*)d_in[2];
    const float* lnw  = (const float*)d_in[3];
    const float* W1   = (const float*)d_in[4];
    const float* g1   = (const float*)d_in[5];
    const float* b1   = (const float*)d_in[6];
    const float* W2   = (const float*)d_in[7];
    const float* g2   = (const float*)d_in[8];
    const float* b2   = (const float*)d_in[9];
    const float* Wout = (const float*)d_in[10];
    float* out = (float*)d_out;

    const int E = in_sizes[1];
    const float invE = 1.0f / (float)E;
    const int mtiles = (E + 127) / 128;

    void *pa, *phh, *pw1, *pw2;
    cudaGetSymbolAddress(&pa, g_a);
    cudaGetSymbolAddress(&phh, g_hh);
    cudaGetSymbolAddress(&pw1, g_w1h);
    cudaGetSymbolAddress(&pw2, g_w2h);

    cudaFuncSetAttribute(bgemm<false>, cudaFuncAttributeMaxDynamicSharedMemorySize, GEMM_SMEM);
    cudaFuncSetAttribute(bgemm<true>,  cudaFuncAttributeMaxDynamicSharedMemorySize, GEMM_SMEM);

    __half* A  = (__half*)pa;    // GEMM1 input, GEMM2 output
    __half* h1 = (__half*)phh;   // GEMM1 output, GEMM2 input

    // 1) gather + LN -> A (fp16), zeroes BN1 stats; weight converts
    gather_ln<<<(E + 7) / 8, 256>>>(x, src, dst, lnw, A, E);
    wconv2<<<512, 512>>>(W1, W2, (__half*)pw1, (__half*)pw2);

    // 2) GEMM1 (+ fused BN1 stats): h1 = A @ W1^T
    bgemm<false><<<dim3(4, mtiles), 256, GEMM_SMEM>>>(A, (__half*)pw1, h1, E);
    finalize_stats<<<1, D>>>(g1, b1, invE);   // sc1/sh1 + BN table + reset

    // 3) GEMM2 with fused BN1+ReLU on A-load (+ fused BN2 stats): A = BN(h1) @ W2^T
    bgemm<true><<<dim3(4, mtiles), 256, GEMM_SMEM>>>(h1, (__half*)pw2, A, E);
    finalize_stats<<<1, D>>>(g2, b2, invE);   // sc2/sh2

    // 4) head reads h2 (=A) with BN2+ReLU
    head<<<(E + 7) / 8, 256>>>(A, Wout, out, E);
}